// round 9
// baseline (speedup 1.0000x reference)
#include <cuda_runtime.h>

// Problem constants (fixed by reference)
#define BS   1024
#define NSEQ 32
#define NBOX 128
#define NCTX 5
#define MAXC 4

// Single fused kernel.
//  - Warps [0, n_tasks): one per (it,b) task; if pval>0, compute the updated
//    parent row and write it to out.
//  - Warps [n_tasks, n_tasks + BS*NSEQ/4): one per (b, 4-row group); copies
//    every non-parent row of the group (parent rows are written exclusively
//    by compute warps; each out row written exactly once).
// Fully parallel: children always have larger indices than parents; parents
// ascend & are unique per batch, so every read in the sequential reference
// sees the ORIGINAL ent_attn.
__global__ __launch_bounds__(256) void topdown_fused_kernel(
    const float* __restrict__ ent,   // [BS,NSEQ,NBOX]
    const float* __restrict__ spo,   // [BS,NSEQ,NBOX,NCTX]
    const int*   __restrict__ ctx,   // [BS,NSEQ,NBOX,NCTX]
    const float* __restrict__ roi,   // [BS,NSEQ,NBOX,NCTX]
    const int*   __restrict__ rcls,  // [BS,NBOX]
    const float* __restrict__ w,     // [BS,NSEQ,NBOX]
    const int*   __restrict__ pidx,  // [L,BS]
    const float* __restrict__ pval,  // [L,BS]
    const int*   __restrict__ cidx,  // [L,BS,MAXC]
    const float* __restrict__ cval,  // [L,BS,MAXC]
    const int*   __restrict__ eidx,  // [L,BS,MAXC]
    const int*   __restrict__ fsmp,  // [L,BS]
    const int*   __restrict__ fslt,  // [L,BS]
    float*       __restrict__ out,   // [BS,NSEQ,NBOX]
    int n_tasks, int L)
{
    const int gwarp = (blockIdx.x * blockDim.x + threadIdx.x) >> 5;
    const int lane  = threadIdx.x & 31;

    if (gwarp >= n_tasks) {
        // -------- copy warp: one per (b, group of 4 rows) --------
        const int idx = gwarp - n_tasks;
        if (idx >= BS * (NSEQ / 4)) return;
        const int b = idx >> 3;         // / 8
        const int g = idx & 7;          // % 8  -> rows 4g..4g+3

        // bitmask of parent rows for batch b (lane = iteration)
        unsigned bit = 0;
        if (lane < L) {
            const int   p = pidx[lane * BS + b];
            const float v = pval[lane * BS + b];
            if (v > 0.f) bit = 1u << p;
        }
        const unsigned rowmask = __reduce_or_sync(0xffffffffu, bit);

        const float4* src = (const float4*)(ent + (((size_t)b * NSEQ + 4 * g) * NBOX));
        float4*       dst = (float4*)(out + (((size_t)b * NSEQ + 4 * g) * NBOX));

        bool  nd[4];
        float4 vv[4];
        #pragma unroll
        for (int q = 0; q < 4; q++) {
            nd[q] = !((rowmask >> (4 * g + q)) & 1u);
            if (nd[q]) vv[q] = __ldcs(src + q * 32 + lane);   // front-batched
        }
        #pragma unroll
        for (int q = 0; q < 4; q++)
            if (nd[q]) __stcs(dst + q * 32 + lane, vv[q]);
        return;
    }

    // ---------------- compute warp: one per (it, b) task ----------------
    const int task = gwarp;
    const int it = task >> 10;          // / BS
    const int b  = task & (BS - 1);     // % BS

    const int base = it * BS + b;
    const float pv = pval[base];
    if (pv <= 0.f) return;
    const int r = pidx[base];

    const int   c0  = cidx[base * MAXC + 0];
    const float cv0 = cval[base * MAXC + 0];
    const int   e0  = eidx[base * MAXC + 0];
    const int   fs  = fsmp[base];
    const int   fl  = fslt[base];
    const int   fe  = eidx[(it * BS + fs) * MAXC + fl];

    // --- transfer[k] = cv0 * sum_box ent[b,c0,box]*cls*spo[b,e0,box,k]*roi[b,e0,box,k] + 1e-6 ---
    // Lane l owns floats [20l, 20l+20) of the 640-float spo/roi rows
    // (= boxes 4l..4l+3, all 5 ctx each). 10 float2 loads per array,
    // 8-byte aligned, fully coalesced.
    const int*   clsrow = rcls + (size_t)b * NBOX;
    const float4 ecv = ((const float4*)(ent + ((size_t)b * NSEQ + c0) * NBOX))[lane];
    const int4   cl  = ((const int4*)clsrow)[lane];

    float ca[4];
    ca[0] = (cl.x == -1) ? 0.f : ecv.x;
    ca[1] = (cl.y == -1) ? 0.f : ecv.y;
    ca[2] = (cl.z == -1) ? 0.f : ecv.z;
    ca[3] = (cl.w == -1) ? 0.f : ecv.w;

    const float2* spov = (const float2*)(spo + ((size_t)b * NSEQ + e0) * NBOX * NCTX) + lane * 10;
    const float2* roiv = (const float2*)(roi + ((size_t)b * NSEQ + e0) * NBOX * NCTX) + lane * 10;

    float t[NCTX] = {0.f, 0.f, 0.f, 0.f, 0.f};
    float2 sv[10], mv[10];
    #pragma unroll
    for (int j = 0; j < 10; j++) sv[j] = __ldcs(spov + j);
    #pragma unroll
    for (int j = 0; j < 10; j++) mv[j] = __ldcs(roiv + j);
    #pragma unroll
    for (int j = 0; j < 10; j++) {
        const int e = 2 * j;            // element e: box=4l+e/5, k=e%5 (compile-time)
        t[(e + 0) % 5] += ca[(e + 0) / 5] * sv[j].x * mv[j].x;
        t[(e + 1) % 5] += ca[(e + 1) / 5] * sv[j].y * mv[j].y;
    }

    #pragma unroll
    for (int o = 16; o > 0; o >>= 1) {
        t[0] += __shfl_xor_sync(0xffffffffu, t[0], o);
        t[1] += __shfl_xor_sync(0xffffffffu, t[1], o);
        t[2] += __shfl_xor_sync(0xffffffffu, t[2], o);
        t[3] += __shfl_xor_sync(0xffffffffu, t[3], o);
        t[4] += __shfl_xor_sync(0xffffffffu, t[4], o);
    }
    float tr[NCTX];
    #pragma unroll
    for (int k = 0; k < NCTX; k++) tr[k] = cv0 * t[k] + 1e-6f;

    // scatter columns: ctx_idx_adjusted[fs, fe, box=0, k] (uniform loads)
    int cols[NCTX];
    const int* cbase = ctx + (((size_t)fs * NSEQ + fe) * NBOX) * NCTX;
    #pragma unroll
    for (int k = 0; k < NCTX; k++) cols[k] = cbase[k];

    // --- row update: each lane owns 4 consecutive boxes of the parent row ---
    const float4 sub = ((const float4*)(ent + ((size_t)b * NSEQ + r) * NBOX))[lane];
    const float4 wv  = __ldcs(((const float4*)(w + ((size_t)b * NSEQ + r) * NBOX)) + lane);

    float su[4]  = {sub.x, sub.y, sub.z, sub.w};
    float wa[4]  = {wv.x, wv.y, wv.z, wv.w};
    int   cla[4] = {cl.x, cl.y, cl.z, cl.w};

    float u[4];
    float mx = 0.f;
    #pragma unroll
    for (int q = 0; q < 4; q++) {
        const int box = lane * 4 + q;
        float add = 1e-6f;
        #pragma unroll
        for (int k = 0; k < NCTX; k++)
            if (cols[k] == box) add = tr[k];
        u[q] = su[q] + add * wa[q];
        mx = fmaxf(mx, fabsf(u[q]));
    }
    #pragma unroll
    for (int o = 16; o > 0; o >>= 1)
        mx = fmaxf(mx, __shfl_xor_sync(0xffffffffu, mx, o));
    const float d = (mx <= 1.f) ? 1.f : mx;

    float rr[4];
    #pragma unroll
    for (int q = 0; q < 4; q++) {
        float vvv = u[q] / d;
        if (cla[q] == -1) vvv = -1.0f;
        rr[q] = vvv;
    }
    float4 res;
    res.x = rr[0]; res.y = rr[1]; res.z = rr[2]; res.w = rr[3];
    __stcs(((float4*)(out + ((size_t)b * NSEQ + r) * NBOX)) + lane, res);
}

extern "C" void kernel_launch(void* const* d_in, const int* in_sizes, int n_in,
                              void* d_out, int out_size) {
    const float* ent  = (const float*)d_in[0];   // ent_attn
    const float* spo  = (const float*)d_in[1];   // spo_attn
    const int*   ctx  = (const int*)  d_in[2];   // ctx_idx_adjusted
    const float* roi  = (const float*)d_in[3];   // roi_mask
    const int*   rcls = (const int*)  d_in[4];   // roi_cls
    const float* w    = (const float*)d_in[5];   // weight_on_children
    const int*   pidx = (const int*)  d_in[6];   // parent_idx [L,BS]
    const float* pval = (const float*)d_in[7];   // parent_valid
    const int*   cidx = (const int*)  d_in[8];   // child_idx
    const float* cval = (const float*)d_in[9];   // child_valid
    const int*   eidx = (const int*)  d_in[10];  // edge_idx
    const int*   fsmp = (const int*)  d_in[11];  // flat_sample
    const int*   fslt = (const int*)  d_in[12];  // flat_slot

    const int L = in_sizes[6] / BS;
    const int n_tasks = L * BS;

    const int total_warps = n_tasks + BS * (NSEQ / 4);  // compute + copy warps
    const int threads = 256;                            // 8 warps/block
    const int blocks = (total_warps * 32 + threads - 1) / threads;

    topdown_fused_kernel<<<blocks, threads>>>(
        ent, spo, ctx, roi, rcls, w,
        pidx, pval, cidx, cval, eidx, fsmp, fslt,
        (float*)d_out, n_tasks, L);
}